// round 4
// baseline (speedup 1.0000x reference)
#include <cuda_runtime.h>
#include <cuda_bf16.h>
#include <cstdint>
#include <math.h>

#define D 32
#define H 128
#define THREADS 256
#define TILE_M 128
#define NROWS 65536

__device__ __forceinline__ uint32_t pack_bf16(__nv_bfloat16 a, __nv_bfloat16 b) {
    return (uint32_t)__bfloat16_as_ushort(a) | ((uint32_t)__bfloat16_as_ushort(b) << 16);
}
__device__ __forceinline__ void split2(float vx, float vy, uint32_t& hi, uint32_t& lo) {
    __nv_bfloat16 hx = __float2bfloat16_rn(vx);
    __nv_bfloat16 hy = __float2bfloat16_rn(vy);
    float rx = vx - __bfloat162float(hx);
    float ry = vy - __bfloat162float(hy);
    hi = pack_bf16(hx, hy);
    lo = pack_bf16(__float2bfloat16_rn(rx), __float2bfloat16_rn(ry));
}
__device__ __forceinline__ float tanh_ap(float x) {
    float y;
    asm("tanh.approx.f32 %0, %1;" : "=f"(y) : "f"(x));
    return y;
}
__device__ __forceinline__ void mma_bf16(float* d, const uint32_t* a, uint32_t b0, uint32_t b1) {
    asm volatile(
        "mma.sync.aligned.m16n8k16.row.col.f32.bf16.bf16.f32 "
        "{%0,%1,%2,%3}, {%4,%5,%6,%7}, {%8,%9}, {%0,%1,%2,%3};"
        : "+f"(d[0]), "+f"(d[1]), "+f"(d[2]), "+f"(d[3])
        : "r"(a[0]), "r"(a[1]), "r"(a[2]), "r"(a[3]), "r"(b0), "r"(b1));
}

// B-frag table: index ((((nt*2 + ks)*2 + hl)*32 + lane)*2 + j)
//   nt 0..15 : z GEMM (B[n][k] = W1[k][n]),  nt 16..31 : v GEMM (B[n][k] = W2[n][k])
#define BF_ENTRIES (32 * 2 * 2 * 32 * 2)   // 8192

extern "C" __global__ void __launch_bounds__(THREADS, 2)
stein_main(const float* __restrict__ x,
           const float* __restrict__ W1,
           const float* __restrict__ b1,
           const float* __restrict__ W2,
           const float* __restrict__ b2,
           const float* __restrict__ theta,
           float* __restrict__ out)
{
    __shared__ uint32_t s_Bf[BF_ENTRIES];        // 32 KB
    __shared__ float s_cs[H];
    __shared__ float s_b1[H];
    __shared__ float s_base[TILE_M];
    __shared__ float s_part[TILE_M][2];

    const int tid  = threadIdx.x;
    const int lane = tid & 31;
    const int w    = tid >> 5;
    const int mh   = w >> 1;                      // 0..3 : 32-row slab
    const int kh   = w & 1;                       // hidden-unit half
    const int row0 = blockIdx.x * TILE_M;

    // ---- build B-frag table in smem (replaces prep kernel) ----
    #pragma unroll
    for (int idx = tid; idx < BF_ENTRIES; idx += THREADS) {
        int j  = idx & 1;
        int l  = (idx >> 1) & 31;
        int hl = (idx >> 6) & 1;
        int ks = (idx >> 7) & 1;
        int nt = idx >> 8;
        int n  = nt * 8 + (l >> 2);
        int k0 = ks * 16 + 2 * (l & 3) + j * 8;
        float w0, w1;
        if (nt < 16) {
            w0 = __ldg(W1 + k0 * H + n);
            w1 = __ldg(W1 + (k0 + 1) * H + n);
        } else {
            int np = n - H;
            w0 = __ldg(W2 + np * D + k0);
            w1 = __ldg(W2 + np * D + k0 + 1);
        }
        uint32_t hi, lo;
        split2(w0, w1, hi, lo);
        s_Bf[idx] = hl ? lo : hi;
    }
    // ---- c_k and b1 ----
    if (tid < H) {
        float c = 0.0f;
        #pragma unroll
        for (int i = 0; i < D; i++)
            c += __ldg(W1 + i * H + tid) * __ldg(W2 + tid * D + i);
        s_cs[tid] = c;
        s_b1[tid] = __ldg(b1 + tid);
    }
    // ---- s_base[r] = theta - x[r].b2 (exact fp32) ----
    if (tid < TILE_M) {
        const float4* xr  = (const float4*)(x + (size_t)(row0 + tid) * D);
        const float4* b2v = (const float4*)b2;
        float s = __ldg(theta);
        #pragma unroll
        for (int i = 0; i < D / 4; i++) {
            float4 a = __ldg(xr + i);
            float4 b = __ldg(b2v + i);
            s = fmaf(-a.x, b.x, s);
            s = fmaf(-a.y, b.y, s);
            s = fmaf(-a.z, b.z, s);
            s = fmaf(-a.w, b.w, s);
        }
        s_base[tid] = s;
    }

    // ---- A fragments straight from gmem (frag order, hi/lo split) ----
    const int Mbase = row0 + mh * 32;
    uint32_t a_hi[2][2][4], a_lo[2][2][4];       // [mt][ks][frag]
    #pragma unroll
    for (int mt = 0; mt < 2; mt++) {
        const int r = Mbase + mt * 16 + (lane >> 2);
        #pragma unroll
        for (int ks = 0; ks < 2; ks++) {
            const int c = ks * 16 + 2 * (lane & 3);
            float2 v00 = __ldg((const float2*)(x + (size_t)r       * D + c));
            float2 v10 = __ldg((const float2*)(x + (size_t)(r + 8) * D + c));
            float2 v01 = __ldg((const float2*)(x + (size_t)r       * D + c + 8));
            float2 v11 = __ldg((const float2*)(x + (size_t)(r + 8) * D + c + 8));
            split2(v00.x, v00.y, a_hi[mt][ks][0], a_lo[mt][ks][0]);
            split2(v10.x, v10.y, a_hi[mt][ks][1], a_lo[mt][ks][1]);
            split2(v01.x, v01.y, a_hi[mt][ks][2], a_lo[mt][ks][2]);
            split2(v11.x, v11.y, a_hi[mt][ks][3], a_lo[mt][ks][3]);
        }
    }
    __syncthreads();

    // ---- mainloop: per-p MMA slab + immediate epilogue into psum ----
    float psum[4] = {0.f, 0.f, 0.f, 0.f};

    #pragma unroll
    for (int p = 0; p < 8; p++) {
        const int ntz = kh * 8 + p;
        const int ntv = 16 + kh * 8 + p;
        uint2 bz[2][2], bv[2][2];                 // [ks][hl]
        #pragma unroll
        for (int ks = 0; ks < 2; ks++)
            #pragma unroll
            for (int hl = 0; hl < 2; hl++) {
                bz[ks][hl] = *(const uint2*)&s_Bf[(((ntz * 2 + ks) * 2 + hl) * 32 + lane) * 2];
                bv[ks][hl] = *(const uint2*)&s_Bf[(((ntv * 2 + ks) * 2 + hl) * 32 + lane) * 2];
            }

        float accz[2][4], accv[2][4];             // [mt][frag]
        #pragma unroll
        for (int mt = 0; mt < 2; mt++)
            #pragma unroll
            for (int e = 0; e < 4; e++) { accz[mt][e] = 0.f; accv[mt][e] = 0.f; }

        #pragma unroll
        for (int mt = 0; mt < 2; mt++)
            #pragma unroll
            for (int ks = 0; ks < 2; ks++) {
                mma_bf16(accz[mt], a_hi[mt][ks], bz[ks][0].x, bz[ks][0].y); // hi*hi
                mma_bf16(accv[mt], a_hi[mt][ks], bv[ks][0].x, bv[ks][0].y);
                mma_bf16(accz[mt], a_hi[mt][ks], bz[ks][1].x, bz[ks][1].y); // hi*lo
                mma_bf16(accv[mt], a_hi[mt][ks], bv[ks][1].x, bv[ks][1].y);
                mma_bf16(accz[mt], a_lo[mt][ks], bz[ks][0].x, bz[ks][0].y); // lo*hi
                mma_bf16(accv[mt], a_lo[mt][ks], bv[ks][0].x, bv[ks][0].y);
            }

        #pragma unroll
        for (int j = 0; j < 2; j++) {
            const int k   = kh * 64 + p * 8 + 2 * (lane & 3) + j;
            const float b1k = s_b1[k];
            const float ck  = s_cs[k];
            #pragma unroll
            for (int mt = 0; mt < 2; mt++)
                #pragma unroll
                for (int rs = 0; rs < 2; rs++) {
                    float z = accz[mt][rs * 2 + j] + b1k;
                    float v = accv[mt][rs * 2 + j];
                    float h = tanh_ap(z);
                    float g = fmaf(-h, h, 1.0f);
                    float& ps = psum[mt * 2 + rs];
                    ps = fmaf(g, ck, ps);
                    ps = fmaf(-h, v, ps);
                }
        }
    }

    // quad reduction over the 4 lanes sharing the same rows
    #pragma unroll
    for (int i = 0; i < 4; i++) {
        psum[i] += __shfl_xor_sync(0xFFFFFFFFu, psum[i], 1);
        psum[i] += __shfl_xor_sync(0xFFFFFFFFu, psum[i], 2);
    }
    if ((lane & 3) == 0) {
        const int rbase = mh * 32 + (lane >> 2);
        s_part[rbase +  0][kh] = psum[0];
        s_part[rbase +  8][kh] = psum[1];
        s_part[rbase + 16][kh] = psum[2];
        s_part[rbase + 24][kh] = psum[3];
    }
    __syncthreads();

    if (tid < TILE_M)
        out[row0 + tid] = s_base[tid] + s_part[tid][0] + s_part[tid][1];
}

extern "C" void kernel_launch(void* const* d_in, const int* in_sizes, int n_in,
                              void* d_out, int out_size)
{
    const float* x     = (const float*)d_in[0];
    const float* W1    = (const float*)d_in[1];
    const float* b1    = (const float*)d_in[2];
    const float* W2    = (const float*)d_in[3];
    const float* b2    = (const float*)d_in[4];
    const float* theta = (const float*)d_in[5];
    float*       out   = (float*)d_out;

    const int nrows = in_sizes[0] / D;          // 65536
    const int grid  = nrows / TILE_M;           // 512

    stein_main<<<grid, THREADS>>>(x, W1, b1, W2, b2, theta, out);
}

// round 5
// speedup vs baseline: 1.7508x; 1.7508x over previous
#include <cuda_runtime.h>
#include <cuda_bf16.h>
#include <cstdint>
#include <math.h>

#define D 32
#define H 128
#define THREADS 128
#define TILE_M 64
#define NROWS 65536

// Precomputed B fragments in exact m16n8k16 HMMA fragment order.
// Index: ((((nt*2 + ks)*2 + hl)*32 + lane)*2 + j)
//   nt 0..15 : z GEMM (B[n][k] = W1[k][n]),  nt 16..31 : v GEMM (B[n][k] = W2[n][k])
__device__ uint32_t g_Bf[32 * 2 * 2 * 32 * 2];   // 32 KB
__device__ float    g_cs[H];                     // c_k = sum_i W1[i,k] * W2[k,i]

__device__ __forceinline__ uint32_t pack_bf16(__nv_bfloat16 a, __nv_bfloat16 b) {
    return (uint32_t)__bfloat16_as_ushort(a) | ((uint32_t)__bfloat16_as_ushort(b) << 16);
}
__device__ __forceinline__ void split2(float vx, float vy, uint32_t& hi, uint32_t& lo) {
    __nv_bfloat16 hx = __float2bfloat16_rn(vx);
    __nv_bfloat16 hy = __float2bfloat16_rn(vy);
    float rx = vx - __bfloat162float(hx);
    float ry = vy - __bfloat162float(hy);
    hi = pack_bf16(hx, hy);
    lo = pack_bf16(__float2bfloat16_rn(rx), __float2bfloat16_rn(ry));
}
__device__ __forceinline__ float tanh_ap(float x) {
    float y;
    asm("tanh.approx.f32 %0, %1;" : "=f"(y) : "f"(x));
    return y;
}
__device__ __forceinline__ void mma_bf16(float* d, const uint32_t* a, uint32_t b0, uint32_t b1) {
    asm volatile(
        "mma.sync.aligned.m16n8k16.row.col.f32.bf16.bf16.f32 "
        "{%0,%1,%2,%3}, {%4,%5,%6,%7}, {%8,%9}, {%0,%1,%2,%3};"
        : "+f"(d[0]), "+f"(d[1]), "+f"(d[2]), "+f"(d[3])
        : "r"(a[0]), "r"(a[1]), "r"(a[2]), "r"(a[3]), "r"(b0), "r"(b1));
}

// ---------------- prep kernel: build B frags + c_k once ----------------
extern "C" __global__ void stein_prep(const float* __restrict__ W1,
                                      const float* __restrict__ W2)
{
    int idx = blockIdx.x * blockDim.x + threadIdx.x;   // 0..8191
    if (idx < 8192) {
        int j  = idx & 1;
        int l  = (idx >> 1) & 31;
        int hl = (idx >> 6) & 1;
        int ks = (idx >> 7) & 1;
        int nt = idx >> 8;
        int n  = nt * 8 + (l >> 2);
        int k0 = ks * 16 + 2 * (l & 3) + j * 8;
        float w0, w1;
        if (nt < 16) {                              // z: B[n][k] = W1[k][n]
            w0 = W1[k0 * H + n];
            w1 = W1[(k0 + 1) * H + n];
        } else {                                    // v: B[n][k] = W2[n'][k]
            int np = n - H;
            w0 = W2[np * D + k0];
            w1 = W2[np * D + k0 + 1];
        }
        uint32_t hi, lo;
        split2(w0, w1, hi, lo);
        g_Bf[idx] = hl ? lo : hi;
    }
    if (idx < H) {
        float c = 0.0f;
        #pragma unroll
        for (int i = 0; i < D; i++)
            c += W1[i * H + idx] * W2[idx * D + i];
        g_cs[idx] = c;
    }
}

// ---------------- main kernel ----------------
extern "C" __global__ void __launch_bounds__(THREADS, 3)
stein_main(const float* __restrict__ x,
           const float* __restrict__ b1,
           const float* __restrict__ b2,
           const float* __restrict__ theta,
           float* __restrict__ out)
{
    __shared__ float s_base[TILE_M];
    __shared__ float s_part[TILE_M][2];

    const int tid  = threadIdx.x;
    const int lane = tid & 31;
    const int w    = tid >> 5;
    const int mh   = w >> 1;        // row half (0: rows 0-31, 1: rows 32-63)
    const int kh   = w & 1;         // hidden-unit half (cols 0-63 / 64-127)
    const int row0 = blockIdx.x * TILE_M;

    // ---- prologue: s_base[r] = theta - x[r].b2 (exact fp32) ----
    if (tid < TILE_M) {
        const float4* xr  = (const float4*)(x + (size_t)(row0 + tid) * D);
        const float4* b2v = (const float4*)b2;
        float s = __ldg(theta);
        #pragma unroll
        for (int i = 0; i < D / 4; i++) {
            float4 a = __ldg(xr + i);
            float4 b = __ldg(b2v + i);
            s = fmaf(-a.x, b.x, s);
            s = fmaf(-a.y, b.y, s);
            s = fmaf(-a.z, b.z, s);
            s = fmaf(-a.w, b.w, s);
        }
        s_base[tid] = s;
    }

    // ---- A fragments straight from gmem (frag order, hi/lo split) ----
    const int Mbase = row0 + mh * 32;
    uint32_t a_hi[2][2][4], a_lo[2][2][4];       // [mt][ks][frag]
    #pragma unroll
    for (int mt = 0; mt < 2; mt++) {
        const int r = Mbase + mt * 16 + (lane >> 2);
        #pragma unroll
        for (int ks = 0; ks < 2; ks++) {
            const int c = ks * 16 + 2 * (lane & 3);
            float2 v00 = __ldg((const float2*)(x + (size_t)r       * D + c));
            float2 v10 = __ldg((const float2*)(x + (size_t)(r + 8) * D + c));
            float2 v01 = __ldg((const float2*)(x + (size_t)r       * D + c + 8));
            float2 v11 = __ldg((const float2*)(x + (size_t)(r + 8) * D + c + 8));
            split2(v00.x, v00.y, a_hi[mt][ks][0], a_lo[mt][ks][0]);
            split2(v10.x, v10.y, a_hi[mt][ks][1], a_lo[mt][ks][1]);
            split2(v01.x, v01.y, a_hi[mt][ks][2], a_lo[mt][ks][2]);
            split2(v11.x, v11.y, a_hi[mt][ks][3], a_lo[mt][ks][3]);
        }
    }

    // ---- mainloop: per-p MMA slab, immediately folded into psum ----
    float psum[4] = {0.f, 0.f, 0.f, 0.f};

    #pragma unroll
    for (int p = 0; p < 8; p++) {
        const int ntz = kh * 8 + p;
        const int ntv = 16 + kh * 8 + p;
        uint2 bz[2][2], bv[2][2];                 // [ks][hl]
        #pragma unroll
        for (int ks = 0; ks < 2; ks++)
            #pragma unroll
            for (int hl = 0; hl < 2; hl++) {
                bz[ks][hl] = *(const uint2*)&g_Bf[(((ntz * 2 + ks) * 2 + hl) * 32 + lane) * 2];
                bv[ks][hl] = *(const uint2*)&g_Bf[(((ntv * 2 + ks) * 2 + hl) * 32 + lane) * 2];
            }

        float accz[2][4], accv[2][4];             // [mt][frag]
        #pragma unroll
        for (int mt = 0; mt < 2; mt++)
            #pragma unroll
            for (int e = 0; e < 4; e++) { accz[mt][e] = 0.f; accv[mt][e] = 0.f; }

        #pragma unroll
        for (int mt = 0; mt < 2; mt++)
            #pragma unroll
            for (int ks = 0; ks < 2; ks++) {
                mma_bf16(accz[mt], a_hi[mt][ks], bz[ks][0].x, bz[ks][0].y); // hi*hi
                mma_bf16(accv[mt], a_hi[mt][ks], bv[ks][0].x, bv[ks][0].y);
                mma_bf16(accz[mt], a_hi[mt][ks], bz[ks][1].x, bz[ks][1].y); // hi*lo
                mma_bf16(accv[mt], a_hi[mt][ks], bv[ks][1].x, bv[ks][1].y);
                mma_bf16(accz[mt], a_lo[mt][ks], bz[ks][0].x, bz[ks][0].y); // lo*hi
                mma_bf16(accv[mt], a_lo[mt][ks], bv[ks][0].x, bv[ks][0].y);
            }

        #pragma unroll
        for (int j = 0; j < 2; j++) {
            const int k   = kh * 64 + p * 8 + 2 * (lane & 3) + j;
            const float b1k = __ldg(b1 + k);
            const float ck  = g_cs[k];
            #pragma unroll
            for (int mt = 0; mt < 2; mt++)
                #pragma unroll
                for (int rs = 0; rs < 2; rs++) {
                    float z = accz[mt][rs * 2 + j] + b1k;
                    float v = accv[mt][rs * 2 + j];
                    float h = tanh_ap(z);
                    float g = fmaf(-h, h, 1.0f);
                    float& ps = psum[mt * 2 + rs];
                    ps = fmaf(g, ck, ps);
                    ps = fmaf(-h, v, ps);
                }
        }
    }

    // quad reduction over the 4 lanes sharing the same rows
    #pragma unroll
    for (int i = 0; i < 4; i++) {
        psum[i] += __shfl_xor_sync(0xFFFFFFFFu, psum[i], 1);
        psum[i] += __shfl_xor_sync(0xFFFFFFFFu, psum[i], 2);
    }
    if ((lane & 3) == 0) {
        const int rbase = mh * 32 + (lane >> 2);
        s_part[rbase +  0][kh] = psum[0];
        s_part[rbase +  8][kh] = psum[1];
        s_part[rbase + 16][kh] = psum[2];
        s_part[rbase + 24][kh] = psum[3];
    }
    __syncthreads();

    if (tid < TILE_M)
        out[row0 + tid] = s_base[tid] + s_part[tid][0] + s_part[tid][1];
}

extern "C" void kernel_launch(void* const* d_in, const int* in_sizes, int n_in,
                              void* d_out, int out_size)
{
    const float* x     = (const float*)d_in[0];
    const float* W1    = (const float*)d_in[1];
    const float* b1    = (const float*)d_in[2];
    const float* W2    = (const float*)d_in[3];
    const float* b2    = (const float*)d_in[4];
    const float* theta = (const float*)d_in[5];
    float*       out   = (float*)d_out;

    const int nrows = in_sizes[0] / D;          // 65536
    const int grid  = nrows / TILE_M;           // 1024

    stein_prep<<<32, 256>>>(W1, W2);
    stein_main<<<grid, THREADS>>>(x, b1, b2, theta, out);
}